// round 16
// baseline (speedup 1.0000x reference)
#include <cuda_runtime.h>
#include <cstdint>

#define B_   32
#define L_   128
#define T_   127
#define DM_  768
#define NH_  12
#define DH_  64
#define FF_  3072
#define NL_  12
#define K_   9
#define NTOK (B_*L_)
#define QKVS 2304

// ---------------- scratch (device globals; no allocation allowed) ----------
__device__ float g_h[NTOK*DM_];
__device__ float g_ctx[NTOK*DM_];
__device__ float g_tmp[NTOK*DM_];
__device__ float g_ffn[NTOK*FF_];          // doubles as QKV buffer [NTOK][2304]
__device__ float g_em[B_*T_*K_];
__device__ float g_llh[B_];

// ---------------- helpers ----------------
__device__ __forceinline__ uint32_t smem_u32(const void* p) {
    uint32_t a;
    asm("{ .reg .u64 t; cvta.to.shared.u64 t, %1; cvt.u32.u64 %0, t; }" : "=r"(a) : "l"(p));
    return a;
}
// mask-based split: hi = truncate-to-tf32(x) via bitmask (exact), lo = x - hi.
#define SPLIT(x, h, l) do {                                            \
    uint32_t _u = __float_as_uint(x) & 0xffffe000u;                    \
    (h) = _u;                                                          \
    (l) = __float_as_uint((x) - __uint_as_float(_u));                  \
} while (0)

__device__ __forceinline__ void mma168(float* c, const uint32_t* a, const uint32_t* b) {
    asm volatile(
        "mma.sync.aligned.m16n8k8.row.col.f32.tf32.tf32.f32 "
        "{%0,%1,%2,%3}, {%4,%5,%6,%7}, {%8,%9}, {%0,%1,%2,%3};"
        : "+f"(c[0]), "+f"(c[1]), "+f"(c[2]), "+f"(c[3])
        : "r"(a[0]), "r"(a[1]), "r"(a[2]), "r"(a[3]), "r"(b[0]), "r"(b[1]));
}
__device__ __forceinline__ void cp16(uint32_t d, const void* s) {
    asm volatile("cp.async.cg.shared.global [%0], [%1], 16;" :: "r"(d), "l"(s) : "memory");
}
#define CP_COMMIT() asm volatile("cp.async.commit_group;" ::: "memory")

// ---------------- 3xTF32 GEMM: 64x64 CTA tile, 128 threads, 4 warps --------
// R15 pipeline (k-loop unrolled by 3, compile-time stage indices);
// regs capped for 7 CTAs/SM (28 warps/SM, smem 7*29184=204KB).
#define A_STG  (64*20)
#define B_STG  (16*72)
#define GT_SMEM ((3*(A_STG + B_STG))*4)     // 29184 bytes

__global__ __launch_bounds__(128, 7)
void gemm_mma(const float* __restrict__ A,
              const float* __restrict__ W0, const float* __restrict__ W1w,
              const float* __restrict__ W2w,
              const float* __restrict__ b0, const float* __restrict__ b1,
              const float* __restrict__ b2,
              float* __restrict__ C, int K, int M, int seg, int act)
{
    extern __shared__ float sm[];
    float* smA = sm;
    float* smB = sm + 3 * A_STG;
    uint32_t sA = smem_u32(smA);
    uint32_t sB = smem_u32(smB);

    int tid = threadIdx.x;
    int wid = tid >> 5, lane = tid & 31;
    int bm = blockIdx.y * 64;
    int bn = blockIdx.x * 64;
    int wm = (wid & 1) * 32;
    int wn = (wid >> 1) * 32;
    int lr = lane >> 2;
    int lc = lane & 3;

    int si = bn / seg;
    const float* Wb = (si == 0) ? W0 : (si == 1) ? W1w : W2w;
    int cw = bn - si * seg;

    int ar = tid >> 1, ak = (tid & 1) * 8;
    const float* pA = A + (size_t)(bm + ar) * K + ak;
    uint32_t dA = sA + (uint32_t)(ar * 20 + ak) * 4;
    int bk = tid >> 3, bnn = (tid & 7) * 8;
    const float* pB = Wb + (size_t)bk * seg + cw + bnn;
    uint32_t dB = sB + (uint32_t)(bk * 72 + bnn) * 4;

    float c[2][4][4];
#pragma unroll
    for (int mt = 0; mt < 2; mt++)
#pragma unroll
        for (int nt = 0; nt < 4; nt++)
#pragma unroll
            for (int q = 0; q < 4; q++) c[mt][nt][q] = 0.f;

    int nc = K >> 4;          // 48 or 192; divisible by 3

    // prologue: stages 0,1
#pragma unroll
    for (int s = 0; s < 2; s++) {
        cp16(dA + s * (A_STG * 4),      pA + s * 16);
        cp16(dA + s * (A_STG * 4) + 16, pA + s * 16 + 4);
        cp16(dB + s * (B_STG * 4),      pB + (size_t)s * 16 * seg);
        cp16(dB + s * (B_STG * 4) + 16, pB + (size_t)s * 16 * seg + 4);
        CP_COMMIT();
    }

#define GSTEP(T, CB, PB) do {                                                  \
    if ((T) == nc - 1) asm volatile("cp.async.wait_group 0;" ::: "memory");    \
    else               asm volatile("cp.async.wait_group 1;" ::: "memory");    \
    __syncthreads();                                                           \
    if ((T) + 2 < nc) {                                                        \
        const float* qa = pA + (size_t)((T) + 2) * 16;                         \
        const float* qb = pB + (size_t)((T) + 2) * 16 * seg;                   \
        cp16(dA + (PB) * (A_STG * 4),      qa);                                \
        cp16(dA + (PB) * (A_STG * 4) + 16, qa + 4);                            \
        cp16(dB + (PB) * (B_STG * 4),      qb);                                \
        cp16(dB + (PB) * (B_STG * 4) + 16, qb + 4);                            \
        CP_COMMIT();                                                           \
    }                                                                          \
    {                                                                          \
        const float* As = smA + (CB) * A_STG;                                  \
        const float* Bs = smB + (CB) * B_STG;                                  \
        _Pragma("unroll")                                                      \
        for (int k8 = 0; k8 < 2; k8++) {                                       \
            int kb = k8 * 8 + lc;                                              \
            uint32_t ah[2][4], al[2][4];                                       \
            _Pragma("unroll")                                                  \
            for (int mt = 0; mt < 2; mt++) {                                   \
                int r0 = wm + mt * 16 + lr;                                    \
                float f0 = As[r0 * 20 + kb];                                   \
                float f1 = As[(r0 + 8) * 20 + kb];                             \
                float f2 = As[r0 * 20 + kb + 4];                               \
                float f3 = As[(r0 + 8) * 20 + kb + 4];                         \
                SPLIT(f0, ah[mt][0], al[mt][0]);                               \
                SPLIT(f1, ah[mt][1], al[mt][1]);                               \
                SPLIT(f2, ah[mt][2], al[mt][2]);                               \
                SPLIT(f3, ah[mt][3], al[mt][3]);                               \
            }                                                                  \
            _Pragma("unroll")                                                  \
            for (int nt = 0; nt < 4; nt++) {                                   \
                int n0 = wn + nt * 8 + lr;                                     \
                float g0 = Bs[kb * 72 + n0];                                   \
                float g1 = Bs[(kb + 4) * 72 + n0];                             \
                uint32_t bh[2], bl[2];                                         \
                SPLIT(g0, bh[0], bl[0]);                                       \
                SPLIT(g1, bh[1], bl[1]);                                       \
                _Pragma("unroll")                                              \
                for (int mt = 0; mt < 2; mt++) {                               \
                    mma168(c[mt][nt], ah[mt], bh);                             \
                    mma168(c[mt][nt], ah[mt], bl);                             \
                    mma168(c[mt][nt], al[mt], bh);                             \
                }                                                              \
            }                                                                  \
        }                                                                      \
    } } while (0)

    for (int t0 = 0; t0 < nc; t0 += 3) {
        GSTEP(t0 + 0, 0, 2);
        GSTEP(t0 + 1, 1, 0);
        GSTEP(t0 + 2, 2, 1);
    }
#undef GSTEP

    // epilogue
    const float* bsel = (si == 0) ? b0 : (si == 1) ? b1 : b2;
#pragma unroll
    for (int nt = 0; nt < 4; nt++) {
        int col = bn + wn + nt * 8 + 2 * lc;
        int cb = col - si * seg;
        float bb0 = bsel[cb], bb1 = bsel[cb + 1];
#pragma unroll
        for (int mt = 0; mt < 2; mt++) {
            int row = bm + wm + mt * 16 + lr;
#pragma unroll
            for (int half = 0; half < 2; half++) {
                float v0 = c[mt][nt][half * 2 + 0] + bb0;
                float v1 = c[mt][nt][half * 2 + 1] + bb1;
                if (act == 1) {
                    v0 = v0 * 0.5f * (1.f + erff(v0 * 0.70710678118654752f));
                    v1 = v1 * 0.5f * (1.f + erff(v1 * 0.70710678118654752f));
                }
                float2 o = make_float2(v0, v1);
                *(float2*)&C[(size_t)(row + half * 8) * M + col] = o;
            }
        }
    }
}

// ---------------- embedding + LayerNorm ----------------
__global__ void embed_ln_kernel(const int* __restrict__ ids, const int* __restrict__ tt,
                                const float* __restrict__ wemb, const float* __restrict__ pemb,
                                const float* __restrict__ temb,
                                const float* __restrict__ g, const float* __restrict__ bta)
{
    __shared__ float red[8];
    int row = blockIdx.x;
    int pos = row & (L_ - 1);
    int tid = threadIdx.x;
    int id = ids[row];
    int ty = tt[row];
    float x[3];
    float s = 0.f;
#pragma unroll
    for (int i = 0; i < 3; i++) {
        int d = tid + i * 256;
        x[i] = wemb[id*DM_ + d] + pemb[pos*DM_ + d] + temb[ty*DM_ + d];
        s += x[i];
    }
    for (int o = 16; o; o >>= 1) s += __shfl_xor_sync(0xffffffffu, s, o);
    if ((tid & 31) == 0) red[tid >> 5] = s;
    __syncthreads();
    if (tid < 8) {
        float v = red[tid];
        for (int o = 4; o; o >>= 1) v += __shfl_xor_sync(0xffu, v, o);
        if (tid == 0) red[0] = v;
    }
    __syncthreads();
    float mean = red[0] * (1.f / DM_);
    __syncthreads();
    float vs = 0.f;
#pragma unroll
    for (int i = 0; i < 3; i++) { float d = x[i] - mean; vs += d * d; }
    for (int o = 16; o; o >>= 1) vs += __shfl_xor_sync(0xffffffffu, vs, o);
    if ((tid & 31) == 0) red[tid >> 5] = vs;
    __syncthreads();
    if (tid < 8) {
        float v = red[tid];
        for (int o = 4; o; o >>= 1) v += __shfl_xor_sync(0xffu, v, o);
        if (tid == 0) red[0] = v;
    }
    __syncthreads();
    float inv = rsqrtf(red[0] * (1.f / DM_) + 1e-12f);
#pragma unroll
    for (int i = 0; i < 3; i++) {
        int d = tid + i * 256;
        g_h[row*DM_ + d] = (x[i] - mean) * inv * g[d] + bta[d];
    }
}

// ---------------- h = LN(h + tmp) ----------------
__global__ void add_ln_kernel(const float* __restrict__ g, const float* __restrict__ bta)
{
    __shared__ float red[8];
    int row = blockIdx.x;
    int tid = threadIdx.x;
    float x[3];
    float s = 0.f;
#pragma unroll
    for (int i = 0; i < 3; i++) {
        int d = tid + i * 256;
        x[i] = g_h[row*DM_ + d] + g_tmp[row*DM_ + d];
        s += x[i];
    }
    for (int o = 16; o; o >>= 1) s += __shfl_xor_sync(0xffffffffu, s, o);
    if ((tid & 31) == 0) red[tid >> 5] = s;
    __syncthreads();
    if (tid < 8) {
        float v = red[tid];
        for (int o = 4; o; o >>= 1) v += __shfl_xor_sync(0xffu, v, o);
        if (tid == 0) red[0] = v;
    }
    __syncthreads();
    float mean = red[0] * (1.f / DM_);
    __syncthreads();
    float vs = 0.f;
#pragma unroll
    for (int i = 0; i < 3; i++) { float d = x[i] - mean; vs += d * d; }
    for (int o = 16; o; o >>= 1) vs += __shfl_xor_sync(0xffffffffu, vs, o);
    if ((tid & 31) == 0) red[tid >> 5] = vs;
    __syncthreads();
    if (tid < 8) {
        float v = red[tid];
        for (int o = 4; o; o >>= 1) v += __shfl_xor_sync(0xffu, v, o);
        if (tid == 0) red[0] = v;
    }
    __syncthreads();
    float inv = rsqrtf(red[0] * (1.f / DM_) + 1e-12f);
#pragma unroll
    for (int i = 0; i < 3; i++) {
        int d = tid + i * 256;
        g_h[row*DM_ + d] = (x[i] - mean) * inv * g[d] + bta[d];
    }
}

// ---------------- fused attention (float4 K/V/Q paths) ---------------------
#define KVP4 17                                   // float4 pitch per row
#define ATTN_SMEM_FLOATS (2*128*KVP4*4 + 16*128 + 8*2*64)
__global__ void attn_kernel(const int* __restrict__ amask)
{
    extern __shared__ float sm[];
    float4* Ksh4 = (float4*)sm;
    float4* Vsh4 = Ksh4 + 128 * KVP4;
    float*  Psh  = sm + 2 * 128 * KVP4 * 4;
    float*  Qsh  = Psh + 16 * 128;
    float4* Qsh4 = (float4*)Qsh;

    int h = blockIdx.x, b = blockIdx.y;
    int tid = threadIdx.x;
    int wid = tid >> 5, lane = tid & 31;
    const float* qkv = g_ffn;
    size_t rbase = (size_t)(b * L_) * QKVS + h * DH_;

    for (int i = tid; i < 128 * 16; i += 256) {
        int r = i >> 4, d4 = i & 15;
        Ksh4[r * KVP4 + d4] = *(const float4*)&qkv[rbase + 768 + (size_t)r * QKVS + d4 * 4];
        Vsh4[r * KVP4 + d4] = *(const float4*)&qkv[rbase + 1536 + (size_t)r * QKVS + d4 * 4];
    }
    __syncthreads();

    int m0 = amask[b * L_ + lane];
    int m1 = amask[b * L_ + lane + 32];
    int m2 = amask[b * L_ + lane + 64];
    int m3 = amask[b * L_ + lane + 96];
    size_t obase = (size_t)(b * L_) * DM_ + h * DH_;

    for (int q0 = wid * 2; q0 < 128; q0 += 16) {
        {
            int qr = lane >> 4, qc = lane & 15;
            Qsh4[(wid * 2 + qr) * 16 + qc] =
                *(const float4*)&qkv[rbase + (size_t)(q0 + qr) * QKVS + qc * 4];
        }
        __syncwarp();

        float s0[4] = {0.f, 0.f, 0.f, 0.f};
        float s1[4] = {0.f, 0.f, 0.f, 0.f};
#pragma unroll 4
        for (int d4 = 0; d4 < 16; d4++) {
            float4 q0v = Qsh4[(wid * 2 + 0) * 16 + d4];
            float4 q1v = Qsh4[(wid * 2 + 1) * 16 + d4];
#pragma unroll
            for (int cc = 0; cc < 4; cc++) {
                float4 kv = Ksh4[(lane + cc * 32) * KVP4 + d4];
                s0[cc] += q0v.x * kv.x; s0[cc] += q0v.y * kv.y;
                s0[cc] += q0v.z * kv.z; s0[cc] += q0v.w * kv.w;
                s1[cc] += q1v.x * kv.x; s1[cc] += q1v.y * kv.y;
                s1[cc] += q1v.z * kv.z; s1[cc] += q1v.w * kv.w;
            }
        }
        int mk[4] = {m0, m1, m2, m3};
#pragma unroll
        for (int cc = 0; cc < 4; cc++) {
            s0[cc] = s0[cc] * 0.125f + (mk[cc] ? 0.f : -1e9f);
            s1[cc] = s1[cc] * 0.125f + (mk[cc] ? 0.f : -1e9f);
        }
        float mx0 = fmaxf(fmaxf(s0[0], s0[1]), fmaxf(s0[2], s0[3]));
        float mx1 = fmaxf(fmaxf(s1[0], s1[1]), fmaxf(s1[2], s1[3]));
        for (int o = 16; o; o >>= 1) {
            mx0 = fmaxf(mx0, __shfl_xor_sync(0xffffffffu, mx0, o));
            mx1 = fmaxf(mx1, __shfl_xor_sync(0xffffffffu, mx1, o));
        }
        float e0[4], e1[4];
        float su0 = 0.f, su1 = 0.f;
#pragma unroll
        for (int cc = 0; cc < 4; cc++) {
            e0[cc] = expf(s0[cc] - mx0); su0 += e0[cc];
            e1[cc] = expf(s1[cc] - mx1); su1 += e1[cc];
        }
        for (int o = 16; o; o >>= 1) {
            su0 += __shfl_xor_sync(0xffffffffu, su0, o);
            su1 += __shfl_xor_sync(0xffffffffu, su1, o);
        }
        float r0 = 1.f / su0, r1 = 1.f / su1;
#pragma unroll
        for (int cc = 0; cc < 4; cc++) {
            Psh[(wid * 2 + 0) * 128 + lane + cc * 32] = e0[cc] * r0;
            Psh[(wid * 2 + 1) * 128 + lane + cc * 32] = e1[cc] * r1;
        }
        __syncwarp();
        const float* Vsh = (const float*)Vsh4;
        float a00 = 0.f, a01 = 0.f, a10 = 0.f, a11 = 0.f;
#pragma unroll 4
        for (int k = 0; k < 128; k++) {
            float p0 = Psh[(wid * 2 + 0) * 128 + k];
            float p1 = Psh[(wid * 2 + 1) * 128 + k];
            float v0 = Vsh[k * (KVP4 * 4) + lane];
            float v1 = Vsh[k * (KVP4 * 4) + lane + 32];
            a00 += p0 * v0; a01 += p0 * v1;
            a10 += p1 * v0; a11 += p1 * v1;
        }
        g_ctx[obase + (size_t)q0 * DM_ + lane]            = a00;
        g_ctx[obase + (size_t)q0 * DM_ + lane + 32]       = a01;
        g_ctx[obase + (size_t)(q0 + 1) * DM_ + lane]      = a10;
        g_ctx[obase + (size_t)(q0 + 1) * DM_ + lane + 32] = a11;
        __syncwarp();
    }
}

// ---------------- emissions ----------------
__global__ void head_kernel(const float* __restrict__ hW, const float* __restrict__ hb)
{
    int t = blockIdx.x, b = blockIdx.y;
    int w = threadIdx.x >> 5, lane = threadIdx.x & 31;
    const float* x = g_h + (size_t)(b * L_ + t + 1) * DM_;
    float s = 0.f;
    for (int d = lane; d < DM_; d += 32) s += x[d] * hW[d * K_ + w];
    for (int o = 16; o; o >>= 1) s += __shfl_xor_sync(0xffffffffu, s, o);
    if (lane == 0) g_em[(size_t)(b * T_ + t) * K_ + w] = s + hb[w];
}

// ---------------- CRF ----------------
__global__ void crf_kernel(const int* __restrict__ amask, const int* __restrict__ y,
                           const float* __restrict__ cs, const float* __restrict__ ce,
                           const float* __restrict__ ct,
                           float* __restrict__ out, int out_size)
{
    __shared__ int hist[(T_ - 1) * K_];
    if (threadIdx.x != 0) return;
    int b = blockIdx.x;
    const float* em = g_em + (size_t)b * T_ * K_;
    const int* mrow = amask + b * L_ + 1;
    const int* yt = y + b * T_;

    int tp = yt[0];
    float num = cs[tp] + em[tp];
    int msum = mrow[0] ? 1 : 0;
    for (int t = 1; t < T_; t++) {
        int tg = yt[t];
        if (mrow[t]) { num += ct[tp * K_ + tg] + em[t * K_ + tg]; msum++; }
        tp = tg;
    }
    num += ce[yt[msum - 1]];

    float alpha[K_], nxt[K_];
    for (int k = 0; k < K_; k++) alpha[k] = cs[k] + em[k];
    for (int t = 1; t < T_; t++) {
        if (!mrow[t]) continue;
        for (int k = 0; k < K_; k++) {
            float mx = -1e30f;
            for (int j = 0; j < K_; j++) mx = fmaxf(mx, alpha[j] + ct[j * K_ + k]);
            float su = 0.f;
            for (int j = 0; j < K_; j++) su += expf(alpha[j] + ct[j * K_ + k] - mx);
            nxt[k] = mx + logf(su) + em[t * K_ + k];
        }
        for (int k = 0; k < K_; k++) alpha[k] = nxt[k];
    }
    float zmx = -1e30f;
    for (int k = 0; k < K_; k++) zmx = fmaxf(zmx, alpha[k] + ce[k]);
    float zs = 0.f;
    for (int k = 0; k < K_; k++) zs += expf(alpha[k] + ce[k] - zmx);
    g_llh[b] = num - (zmx + logf(zs));

    float sc[K_], nv[K_];
    for (int k = 0; k < K_; k++) sc[k] = cs[k] + em[k];
    for (int t = 1; t < T_; t++) {
        for (int k = 0; k < K_; k++) {
            int bj = 0;
            float bv = sc[0] + ct[k];
            for (int j = 1; j < K_; j++) {
                float c = sc[j] + ct[j * K_ + k];
                if (c > bv) { bv = c; bj = j; }
            }
            hist[(t - 1) * K_ + k] = bj;
            nv[k] = bv + em[t * K_ + k];
        }
        if (mrow[t]) for (int k = 0; k < K_; k++) sc[k] = nv[k];
    }
    int last = 0;
    float bvv = sc[0] + ce[0];
    for (int j = 1; j < K_; j++) {
        float c = sc[j] + ce[j];
        if (c > bvv) { bvv = c; last = j; }
    }
    int dec[T_];
    int tag = last;
    for (int i = T_ - 2; i >= 0; i--) {
        dec[i + 1] = tag;
        int prev = hist[i * K_ + tag];
        if (mrow[i + 1]) tag = prev;
    }
    dec[0] = tag;

    if (out_size >= 1 + B_ * T_) {
        for (int t = 0; t < T_; t++) out[1 + b * T_ + t] = (float)dec[t];
    } else if (out_size == B_ * T_) {
        int* oi = (int*)out;
        for (int t = 0; t < T_; t++) oi[b * T_ + t] = dec[t];
    }
}

__global__ void llh_kernel(float* __restrict__ out, int out_size)
{
    int tid = threadIdx.x;
    float v = (tid < B_) ? g_llh[tid] : 0.f;
    for (int o = 16; o; o >>= 1) v += __shfl_xor_sync(0xffffffffu, v, o);
    if (tid == 0 && out_size != B_ * T_) out[0] = v * (1.f / B_);
    int base = (out_size >= 1 + B_ * T_) ? (1 + B_ * T_)
             : ((out_size == B_ * T_) ? B_ * T_ : 1);
    for (int i = base + tid; i < out_size; i += 32) out[i] = 0.f;
}

// ---------------- launcher ----------------
extern "C" void kernel_launch(void* const* d_in, const int* in_sizes, int n_in,
                              void* d_out, int out_size)
{
    const int*   ids  = (const int*)d_in[0];
    const int*   am   = (const int*)d_in[1];
    const int*   tt   = (const int*)d_in[2];
    const int*   yt   = (const int*)d_in[3];
    const float* wemb = (const float*)d_in[4];
    const float* pemb = (const float*)d_in[5];
    const float* temb = (const float*)d_in[6];
    const float* eg   = (const float*)d_in[7];
    const float* eb   = (const float*)d_in[8];
    const float* Wq   = (const float*)d_in[9];
    const float* bq   = (const float*)d_in[10];
    const float* Wk   = (const float*)d_in[11];
    const float* bk   = (const float*)d_in[12];
    const float* Wv   = (const float*)d_in[13];
    const float* bv   = (const float*)d_in[14];
    const float* Wo   = (const float*)d_in[15];
    const float* bo   = (const float*)d_in[16];
    const float* l1g  = (const float*)d_in[17];
    const float* l1b  = (const float*)d_in[18];
    const float* W1   = (const float*)d_in[19];
    const float* b1   = (const float*)d_in[20];
    const float* W2   = (const float*)d_in[21];
    const float* b2   = (const float*)d_in[22];
    const float* l2g  = (const float*)d_in[23];
    const float* l2b  = (const float*)d_in[24];
    const float* hW   = (const float*)d_in[25];
    const float* hb   = (const float*)d_in[26];
    const float* cs   = (const float*)d_in[27];
    const float* ce   = (const float*)d_in[28];
    const float* ctr  = (const float*)d_in[29];

    static float *p_h = nullptr, *p_ctx, *p_tmp, *p_ffn;
    if (!p_h) {
        cudaGetSymbolAddress((void**)&p_h,   g_h);
        cudaGetSymbolAddress((void**)&p_ctx, g_ctx);
        cudaGetSymbolAddress((void**)&p_tmp, g_tmp);
        cudaGetSymbolAddress((void**)&p_ffn, g_ffn);
        cudaFuncSetAttribute(attn_kernel, cudaFuncAttributeMaxDynamicSharedMemorySize,
                             ATTN_SMEM_FLOATS * 4);
        cudaFuncSetAttribute(gemm_mma, cudaFuncAttributeMaxDynamicSharedMemorySize,
                             GT_SMEM);
    }

    embed_ln_kernel<<<NTOK, 256>>>(ids, tt, wemb, pemb, temb, eg, eb);

    dim3 gG_qkv(QKVS / 64, NTOK / 64);     // 36 x 64
    dim3 gG_dm(DM_ / 64, NTOK / 64);       // 12 x 64
    dim3 gG_ff(FF_ / 64, NTOK / 64);       // 48 x 64

    for (int l = 0; l < NL_; l++) {
        size_t wOff = (size_t)l * DM_ * DM_;
        // ---- fused QKV: C = h @ [Wq|Wk|Wv] + [bq|bk|bv] ----
        gemm_mma<<<gG_qkv, 128, GT_SMEM>>>(p_h, Wq + wOff, Wk + wOff, Wv + wOff,
                                           bq + l * DM_, bk + l * DM_, bv + l * DM_,
                                           p_ffn, DM_, QKVS, 768, 0);
        // ---- attention ----
        attn_kernel<<<dim3(NH_, B_), 256, ATTN_SMEM_FLOATS * 4>>>(am);
        // ---- output proj ----
        gemm_mma<<<gG_dm, 128, GT_SMEM>>>(p_ctx, Wo + wOff, Wo + wOff, Wo + wOff,
                                          bo + l * DM_, bo + l * DM_, bo + l * DM_,
                                          p_tmp, DM_, DM_, DM_, 0);
        add_ln_kernel<<<NTOK, 256>>>(l1g + l * DM_, l1b + l * DM_);
        // ---- FFN ----
        gemm_mma<<<gG_ff, 128, GT_SMEM>>>(p_h, W1 + (size_t)l * DM_ * FF_,
                                          W1 + (size_t)l * DM_ * FF_,
                                          W1 + (size_t)l * DM_ * FF_,
                                          b1 + l * FF_, b1 + l * FF_, b1 + l * FF_,
                                          p_ffn, DM_, FF_, FF_, 1);
        gemm_mma<<<gG_dm, 128, GT_SMEM>>>(p_ffn, W2 + (size_t)l * FF_ * DM_,
                                          W2 + (size_t)l * FF_ * DM_,
                                          W2 + (size_t)l * FF_ * DM_,
                                          b2 + l * DM_, b2 + l * DM_, b2 + l * DM_,
                                          p_tmp, FF_, DM_, DM_, 0);
        add_ln_kernel<<<NTOK, 256>>>(l2g + l * DM_, l2b + l * DM_);
    }

    head_kernel<<<dim3(T_, B_), 288>>>(hW, hb);
    crf_kernel<<<B_, 32>>>(am, yt, cs, ce, ctr, (float*)d_out, out_size);
    llh_kernel<<<1, 32>>>((float*)d_out, out_size);
}

// round 17
// speedup vs baseline: 1.0378x; 1.0378x over previous
#include <cuda_runtime.h>
#include <cstdint>

#define B_   32
#define L_   128
#define T_   127
#define DM_  768
#define NH_  12
#define DH_  64
#define FF_  3072
#define NL_  12
#define K_   9
#define NTOK (B_*L_)
#define QKVS 2304

// ---------------- scratch (device globals; no allocation allowed) ----------
__device__ float g_h[NTOK*DM_];
__device__ float g_ctx[NTOK*DM_];
__device__ float g_tmp[NTOK*DM_];
__device__ float g_ffn[NTOK*FF_];          // doubles as QKV buffer [NTOK][2304]
__device__ float g_em[B_*T_*K_];
__device__ float g_llh[B_];
__device__ int   g_crf_done;

// ---------------- helpers ----------------
__device__ __forceinline__ uint32_t smem_u32(const void* p) {
    uint32_t a;
    asm("{ .reg .u64 t; cvta.to.shared.u64 t, %1; cvt.u32.u64 %0, t; }" : "=r"(a) : "l"(p));
    return a;
}
// mask-based split: hi = truncate-to-tf32(x) via bitmask (exact), lo = x - hi.
#define SPLIT(x, h, l) do {                                            \
    uint32_t _u = __float_as_uint(x) & 0xffffe000u;                    \
    (h) = _u;                                                          \
    (l) = __float_as_uint((x) - __uint_as_float(_u));                  \
} while (0)

__device__ __forceinline__ void mma168(float* c, const uint32_t* a, const uint32_t* b) {
    asm volatile(
        "mma.sync.aligned.m16n8k8.row.col.f32.tf32.tf32.f32 "
        "{%0,%1,%2,%3}, {%4,%5,%6,%7}, {%8,%9}, {%0,%1,%2,%3};"
        : "+f"(c[0]), "+f"(c[1]), "+f"(c[2]), "+f"(c[3])
        : "r"(a[0]), "r"(a[1]), "r"(a[2]), "r"(a[3]), "r"(b[0]), "r"(b[1]));
}
__device__ __forceinline__ void cp16(uint32_t d, const void* s) {
    asm volatile("cp.async.cg.shared.global [%0], [%1], 16;" :: "r"(d), "l"(s) : "memory");
}
#define CP_COMMIT() asm volatile("cp.async.commit_group;" ::: "memory")

// ---------------- 3xTF32 GEMM: 64x64 CTA tile, 128 threads, 4 warps --------
// R15 pipeline verbatim (k-loop unrolled by 3, compile-time stage indices).
#define A_STG  (64*20)
#define B_STG  (16*72)
#define GT_SMEM ((3*(A_STG + B_STG))*4)     // 29184 bytes

__global__ __launch_bounds__(128, 6)
void gemm_mma(const float* __restrict__ A,
              const float* __restrict__ W0, const float* __restrict__ W1w,
              const float* __restrict__ W2w,
              const float* __restrict__ b0, const float* __restrict__ b1,
              const float* __restrict__ b2,
              float* __restrict__ C, int K, int M, int seg, int act)
{
    extern __shared__ float sm[];
    float* smA = sm;
    float* smB = sm + 3 * A_STG;
    uint32_t sA = smem_u32(smA);
    uint32_t sB = smem_u32(smB);

    int tid = threadIdx.x;
    int wid = tid >> 5, lane = tid & 31;
    int bm = blockIdx.y * 64;
    int bn = blockIdx.x * 64;
    int wm = (wid & 1) * 32;
    int wn = (wid >> 1) * 32;
    int lr = lane >> 2;
    int lc = lane & 3;

    int si = bn / seg;
    const float* Wb = (si == 0) ? W0 : (si == 1) ? W1w : W2w;
    int cw = bn - si * seg;

    int ar = tid >> 1, ak = (tid & 1) * 8;
    const float* pA = A + (size_t)(bm + ar) * K + ak;
    uint32_t dA = sA + (uint32_t)(ar * 20 + ak) * 4;
    int bk = tid >> 3, bnn = (tid & 7) * 8;
    const float* pB = Wb + (size_t)bk * seg + cw + bnn;
    uint32_t dB = sB + (uint32_t)(bk * 72 + bnn) * 4;

    float c[2][4][4];
#pragma unroll
    for (int mt = 0; mt < 2; mt++)
#pragma unroll
        for (int nt = 0; nt < 4; nt++)
#pragma unroll
            for (int q = 0; q < 4; q++) c[mt][nt][q] = 0.f;

    int nc = K >> 4;          // 48 or 192; divisible by 3

    // prologue: stages 0,1
#pragma unroll
    for (int s = 0; s < 2; s++) {
        cp16(dA + s * (A_STG * 4),      pA + s * 16);
        cp16(dA + s * (A_STG * 4) + 16, pA + s * 16 + 4);
        cp16(dB + s * (B_STG * 4),      pB + (size_t)s * 16 * seg);
        cp16(dB + s * (B_STG * 4) + 16, pB + (size_t)s * 16 * seg + 4);
        CP_COMMIT();
    }

#define GSTEP(T, CB, PB) do {                                                  \
    if ((T) == nc - 1) asm volatile("cp.async.wait_group 0;" ::: "memory");    \
    else               asm volatile("cp.async.wait_group 1;" ::: "memory");    \
    __syncthreads();                                                           \
    if ((T) + 2 < nc) {                                                        \
        const float* qa = pA + (size_t)((T) + 2) * 16;                         \
        const float* qb = pB + (size_t)((T) + 2) * 16 * seg;                   \
        cp16(dA + (PB) * (A_STG * 4),      qa);                                \
        cp16(dA + (PB) * (A_STG * 4) + 16, qa + 4);                            \
        cp16(dB + (PB) * (B_STG * 4),      qb);                                \
        cp16(dB + (PB) * (B_STG * 4) + 16, qb + 4);                            \
        CP_COMMIT();                                                           \
    }                                                                          \
    {                                                                          \
        const float* As = smA + (CB) * A_STG;                                  \
        const float* Bs = smB + (CB) * B_STG;                                  \
        _Pragma("unroll")                                                      \
        for (int k8 = 0; k8 < 2; k8++) {                                       \
            int kb = k8 * 8 + lc;                                              \
            uint32_t ah[2][4], al[2][4];                                       \
            _Pragma("unroll")                                                  \
            for (int mt = 0; mt < 2; mt++) {                                   \
                int r0 = wm + mt * 16 + lr;                                    \
                float f0 = As[r0 * 20 + kb];                                   \
                float f1 = As[(r0 + 8) * 20 + kb];                             \
                float f2 = As[r0 * 20 + kb + 4];                               \
                float f3 = As[(r0 + 8) * 20 + kb + 4];                         \
                SPLIT(f0, ah[mt][0], al[mt][0]);                               \
                SPLIT(f1, ah[mt][1], al[mt][1]);                               \
                SPLIT(f2, ah[mt][2], al[mt][2]);                               \
                SPLIT(f3, ah[mt][3], al[mt][3]);                               \
            }                                                                  \
            _Pragma("unroll")                                                  \
            for (int nt = 0; nt < 4; nt++) {                                   \
                int n0 = wn + nt * 8 + lr;                                     \
                float g0 = Bs[kb * 72 + n0];                                   \
                float g1 = Bs[(kb + 4) * 72 + n0];                             \
                uint32_t bh[2], bl[2];                                         \
                SPLIT(g0, bh[0], bl[0]);                                       \
                SPLIT(g1, bh[1], bl[1]);                                       \
                _Pragma("unroll")                                              \
                for (int mt = 0; mt < 2; mt++) {                               \
                    mma168(c[mt][nt], ah[mt], bh);                             \
                    mma168(c[mt][nt], ah[mt], bl);                             \
                    mma168(c[mt][nt], al[mt], bh);                             \
                }                                                              \
            }                                                                  \
        }                                                                      \
    } } while (0)

    for (int t0 = 0; t0 < nc; t0 += 3) {
        GSTEP(t0 + 0, 0, 2);
        GSTEP(t0 + 1, 1, 0);
        GSTEP(t0 + 2, 2, 1);
    }
#undef GSTEP

    // epilogue
    const float* bsel = (si == 0) ? b0 : (si == 1) ? b1 : b2;
#pragma unroll
    for (int nt = 0; nt < 4; nt++) {
        int col = bn + wn + nt * 8 + 2 * lc;
        int cb = col - si * seg;
        float bb0 = bsel[cb], bb1 = bsel[cb + 1];
#pragma unroll
        for (int mt = 0; mt < 2; mt++) {
            int row = bm + wm + mt * 16 + lr;
#pragma unroll
            for (int half = 0; half < 2; half++) {
                float v0 = c[mt][nt][half * 2 + 0] + bb0;
                float v1 = c[mt][nt][half * 2 + 1] + bb1;
                if (act == 1) {
                    v0 = v0 * 0.5f * (1.f + erff(v0 * 0.70710678118654752f));
                    v1 = v1 * 0.5f * (1.f + erff(v1 * 0.70710678118654752f));
                }
                float2 o = make_float2(v0, v1);
                *(float2*)&C[(size_t)(row + half * 8) * M + col] = o;
            }
        }
    }
}

// ---------------- embedding + LayerNorm (float4, 192 threads) --------------
__global__ void embed_ln_kernel(const int* __restrict__ ids, const int* __restrict__ tt,
                                const float* __restrict__ wemb, const float* __restrict__ pemb,
                                const float* __restrict__ temb,
                                const float* __restrict__ g, const float* __restrict__ bta)
{
    __shared__ float red[6];
    int row = blockIdx.x;
    int pos = row & (L_ - 1);
    int tid = threadIdx.x;          // 192 threads, 1 float4 each
    int id = ids[row];
    int ty = tt[row];
    float4 w = *(const float4*)&wemb[(size_t)id * DM_ + tid * 4];
    float4 p = *(const float4*)&pemb[(size_t)pos * DM_ + tid * 4];
    float4 t = *(const float4*)&temb[(size_t)ty * DM_ + tid * 4];
    float4 x = make_float4(w.x + p.x + t.x, w.y + p.y + t.y,
                           w.z + p.z + t.z, w.w + p.w + t.w);
    float s = x.x + x.y + x.z + x.w;
    for (int o = 16; o; o >>= 1) s += __shfl_xor_sync(0xffffffffu, s, o);
    if ((tid & 31) == 0) red[tid >> 5] = s;
    __syncthreads();
    float mean = (red[0] + red[1] + red[2] + red[3] + red[4] + red[5]) * (1.f / DM_);
    __syncthreads();
    float dx = x.x - mean, dy = x.y - mean, dz = x.z - mean, dw = x.w - mean;
    float vs = dx * dx + dy * dy + dz * dz + dw * dw;
    for (int o = 16; o; o >>= 1) vs += __shfl_xor_sync(0xffffffffu, vs, o);
    if ((tid & 31) == 0) red[tid >> 5] = vs;
    __syncthreads();
    float inv = rsqrtf((red[0] + red[1] + red[2] + red[3] + red[4] + red[5]) * (1.f / DM_)
                       + 1e-12f);
    float4 gg = *(const float4*)&g[tid * 4];
    float4 bb = *(const float4*)&bta[tid * 4];
    float4 o = make_float4(dx * inv * gg.x + bb.x, dy * inv * gg.y + bb.y,
                           dz * inv * gg.z + bb.z, dw * inv * gg.w + bb.w);
    *(float4*)&g_h[(size_t)row * DM_ + tid * 4] = o;
}

// ---------------- h = LN(h + tmp) (float4, 192 threads) --------------------
__global__ void add_ln_kernel(const float* __restrict__ g, const float* __restrict__ bta)
{
    __shared__ float red[6];
    int row = blockIdx.x;
    int tid = threadIdx.x;
    float4 a = *(const float4*)&g_h[(size_t)row * DM_ + tid * 4];
    float4 b = *(const float4*)&g_tmp[(size_t)row * DM_ + tid * 4];
    float4 x = make_float4(a.x + b.x, a.y + b.y, a.z + b.z, a.w + b.w);
    float s = x.x + x.y + x.z + x.w;
    for (int o = 16; o; o >>= 1) s += __shfl_xor_sync(0xffffffffu, s, o);
    if ((tid & 31) == 0) red[tid >> 5] = s;
    __syncthreads();
    float mean = (red[0] + red[1] + red[2] + red[3] + red[4] + red[5]) * (1.f / DM_);
    __syncthreads();
    float dx = x.x - mean, dy = x.y - mean, dz = x.z - mean, dw = x.w - mean;
    float vs = dx * dx + dy * dy + dz * dz + dw * dw;
    for (int o = 16; o; o >>= 1) vs += __shfl_xor_sync(0xffffffffu, vs, o);
    if ((tid & 31) == 0) red[tid >> 5] = vs;
    __syncthreads();
    float inv = rsqrtf((red[0] + red[1] + red[2] + red[3] + red[4] + red[5]) * (1.f / DM_)
                       + 1e-12f);
    float4 gg = *(const float4*)&g[tid * 4];
    float4 bb = *(const float4*)&bta[tid * 4];
    float4 o = make_float4(dx * inv * gg.x + bb.x, dy * inv * gg.y + bb.y,
                           dz * inv * gg.z + bb.z, dw * inv * gg.w + bb.w);
    *(float4*)&g_h[(size_t)row * DM_ + tid * 4] = o;
}

// ---------------- fused attention (float4 K/V/Q paths) ---------------------
#define KVP4 17                                   // float4 pitch per row
#define ATTN_SMEM_FLOATS (2*128*KVP4*4 + 16*128 + 8*2*64)
__global__ void attn_kernel(const int* __restrict__ amask)
{
    extern __shared__ float sm[];
    float4* Ksh4 = (float4*)sm;
    float4* Vsh4 = Ksh4 + 128 * KVP4;
    float*  Psh  = sm + 2 * 128 * KVP4 * 4;
    float*  Qsh  = Psh + 16 * 128;
    float4* Qsh4 = (float4*)Qsh;

    int h = blockIdx.x, b = blockIdx.y;
    int tid = threadIdx.x;
    int wid = tid >> 5, lane = tid & 31;
    const float* qkv = g_ffn;
    size_t rbase = (size_t)(b * L_) * QKVS + h * DH_;

    for (int i = tid; i < 128 * 16; i += 256) {
        int r = i >> 4, d4 = i & 15;
        Ksh4[r * KVP4 + d4] = *(const float4*)&qkv[rbase + 768 + (size_t)r * QKVS + d4 * 4];
        Vsh4[r * KVP4 + d4] = *(const float4*)&qkv[rbase + 1536 + (size_t)r * QKVS + d4 * 4];
    }
    __syncthreads();

    int m0 = amask[b * L_ + lane];
    int m1 = amask[b * L_ + lane + 32];
    int m2 = amask[b * L_ + lane + 64];
    int m3 = amask[b * L_ + lane + 96];
    size_t obase = (size_t)(b * L_) * DM_ + h * DH_;

    for (int q0 = wid * 2; q0 < 128; q0 += 16) {
        {
            int qr = lane >> 4, qc = lane & 15;
            Qsh4[(wid * 2 + qr) * 16 + qc] =
                *(const float4*)&qkv[rbase + (size_t)(q0 + qr) * QKVS + qc * 4];
        }
        __syncwarp();

        float s0[4] = {0.f, 0.f, 0.f, 0.f};
        float s1[4] = {0.f, 0.f, 0.f, 0.f};
#pragma unroll 4
        for (int d4 = 0; d4 < 16; d4++) {
            float4 q0v = Qsh4[(wid * 2 + 0) * 16 + d4];
            float4 q1v = Qsh4[(wid * 2 + 1) * 16 + d4];
#pragma unroll
            for (int cc = 0; cc < 4; cc++) {
                float4 kv = Ksh4[(lane + cc * 32) * KVP4 + d4];
                s0[cc] += q0v.x * kv.x; s0[cc] += q0v.y * kv.y;
                s0[cc] += q0v.z * kv.z; s0[cc] += q0v.w * kv.w;
                s1[cc] += q1v.x * kv.x; s1[cc] += q1v.y * kv.y;
                s1[cc] += q1v.z * kv.z; s1[cc] += q1v.w * kv.w;
            }
        }
        int mk[4] = {m0, m1, m2, m3};
#pragma unroll
        for (int cc = 0; cc < 4; cc++) {
            s0[cc] = s0[cc] * 0.125f + (mk[cc] ? 0.f : -1e9f);
            s1[cc] = s1[cc] * 0.125f + (mk[cc] ? 0.f : -1e9f);
        }
        float mx0 = fmaxf(fmaxf(s0[0], s0[1]), fmaxf(s0[2], s0[3]));
        float mx1 = fmaxf(fmaxf(s1[0], s1[1]), fmaxf(s1[2], s1[3]));
        for (int o = 16; o; o >>= 1) {
            mx0 = fmaxf(mx0, __shfl_xor_sync(0xffffffffu, mx0, o));
            mx1 = fmaxf(mx1, __shfl_xor_sync(0xffffffffu, mx1, o));
        }
        float e0[4], e1[4];
        float su0 = 0.f, su1 = 0.f;
#pragma unroll
        for (int cc = 0; cc < 4; cc++) {
            e0[cc] = expf(s0[cc] - mx0); su0 += e0[cc];
            e1[cc] = expf(s1[cc] - mx1); su1 += e1[cc];
        }
        for (int o = 16; o; o >>= 1) {
            su0 += __shfl_xor_sync(0xffffffffu, su0, o);
            su1 += __shfl_xor_sync(0xffffffffu, su1, o);
        }
        float r0 = 1.f / su0, r1 = 1.f / su1;
#pragma unroll
        for (int cc = 0; cc < 4; cc++) {
            Psh[(wid * 2 + 0) * 128 + lane + cc * 32] = e0[cc] * r0;
            Psh[(wid * 2 + 1) * 128 + lane + cc * 32] = e1[cc] * r1;
        }
        __syncwarp();
        const float* Vsh = (const float*)Vsh4;
        float a00 = 0.f, a01 = 0.f, a10 = 0.f, a11 = 0.f;
#pragma unroll 4
        for (int k = 0; k < 128; k++) {
            float p0 = Psh[(wid * 2 + 0) * 128 + k];
            float p1 = Psh[(wid * 2 + 1) * 128 + k];
            float v0 = Vsh[k * (KVP4 * 4) + lane];
            float v1 = Vsh[k * (KVP4 * 4) + lane + 32];
            a00 += p0 * v0; a01 += p0 * v1;
            a10 += p1 * v0; a11 += p1 * v1;
        }
        g_ctx[obase + (size_t)q0 * DM_ + lane]            = a00;
        g_ctx[obase + (size_t)q0 * DM_ + lane + 32]       = a01;
        g_ctx[obase + (size_t)(q0 + 1) * DM_ + lane]      = a10;
        g_ctx[obase + (size_t)(q0 + 1) * DM_ + lane + 32] = a11;
        __syncwarp();
    }
}

// ---------------- emissions ----------------
__global__ void head_kernel(const float* __restrict__ hW, const float* __restrict__ hb)
{
    int t = blockIdx.x, b = blockIdx.y;
    int w = threadIdx.x >> 5, lane = threadIdx.x & 31;
    const float* x = g_h + (size_t)(b * L_ + t + 1) * DM_;
    float s = 0.f;
    for (int d = lane; d < DM_; d += 32) s += x[d] * hW[d * K_ + w];
    for (int o = 16; o; o >>= 1) s += __shfl_xor_sync(0xffffffffu, s, o);
    if (lane == 0) g_em[(size_t)(b * T_ + t) * K_ + w] = s + hb[w];
}

// ---------------- CRF (fused llh finalize via atomic last-block) -----------
__global__ void crf_kernel(const int* __restrict__ amask, const int* __restrict__ y,
                           const float* __restrict__ cs, const float* __restrict__ ce,
                           const float* __restrict__ ct,
                           float* __restrict__ out, int out_size)
{
    __shared__ int hist[(T_ - 1) * K_];
    if (threadIdx.x != 0) return;
    int b = blockIdx.x;
    const float* em = g_em + (size_t)b * T_ * K_;
    const int* mrow = amask + b * L_ + 1;
    const int* yt = y + b * T_;

    int tp = yt[0];
    float num = cs[tp] + em[tp];
    int msum = mrow[0] ? 1 : 0;
    for (int t = 1; t < T_; t++) {
        int tg = yt[t];
        if (mrow[t]) { num += ct[tp * K_ + tg] + em[t * K_ + tg]; msum++; }
        tp = tg;
    }
    num += ce[yt[msum - 1]];

    float alpha[K_], nxt[K_];
    for (int k = 0; k < K_; k++) alpha[k] = cs[k] + em[k];
    for (int t = 1; t < T_; t++) {
        if (!mrow[t]) continue;
        for (int k = 0; k < K_; k++) {
            float mx = -1e30f;
            for (int j = 0; j < K_; j++) mx = fmaxf(mx, alpha[j] + ct[j * K_ + k]);
            float su = 0.f;
            for (int j = 0; j < K_; j++) su += expf(alpha[j] + ct[j * K_ + k] - mx);
            nxt[k] = mx + logf(su) + em[t * K_ + k];
        }
        for (int k = 0; k < K_; k++) alpha[k] = nxt[k];
    }
    float zmx = -1e30f;
    for (int k = 0; k < K_; k++) zmx = fmaxf(zmx, alpha[k] + ce[k]);
    float zs = 0.f;
    for (int k = 0; k < K_; k++) zs += expf(alpha[k] + ce[k] - zmx);
    g_llh[b] = num - (zmx + logf(zs));

    float sc[K_], nv[K_];
    for (int k = 0; k < K_; k++) sc[k] = cs[k] + em[k];
    for (int t = 1; t < T_; t++) {
        for (int k = 0; k < K_; k++) {
            int bj = 0;
            float bv = sc[0] + ct[k];
            for (int j = 1; j < K_; j++) {
                float c = sc[j] + ct[j * K_ + k];
                if (c > bv) { bv = c; bj = j; }
            }
            hist[(t - 1) * K_ + k] = bj;
            nv[k] = bv + em[t * K_ + k];
        }
        if (mrow[t]) for (int k = 0; k < K_; k++) sc[k] = nv[k];
    }
    int last = 0;
    float bvv = sc[0] + ce[0];
    for (int j = 1; j < K_; j++) {
        float c = sc[j] + ce[j];
        if (c > bvv) { bvv = c; last = j; }
    }
    int dec[T_];
    int tag = last;
    for (int i = T_ - 2; i >= 0; i--) {
        dec[i + 1] = tag;
        int prev = hist[i * K_ + tag];
        if (mrow[i + 1]) tag = prev;
    }
    dec[0] = tag;

    if (out_size >= 1 + B_ * T_) {
        for (int t = 0; t < T_; t++) out[1 + b * T_ + t] = (float)dec[t];
    } else if (out_size == B_ * T_) {
        int* oi = (int*)out;
        for (int t = 0; t < T_; t++) oi[b * T_ + t] = dec[t];
    }

    // last block finalizes llh (deterministic: fixed summation order)
    __threadfence();
    int done = atomicAdd(&g_crf_done, 1);
    if (done == B_ - 1) {
        g_crf_done = 0;                      // reset for next graph replay
        float s = 0.f;
        for (int i = 0; i < B_; i++) s += g_llh[i];
        if (out_size != B_ * T_) out[0] = s * (1.f / B_);
        int base = (out_size >= 1 + B_ * T_) ? (1 + B_ * T_)
                 : ((out_size == B_ * T_) ? B_ * T_ : 1);
        for (int i = base; i < out_size; i++) out[i] = 0.f;
    }
}

// ---------------- launcher ----------------
extern "C" void kernel_launch(void* const* d_in, const int* in_sizes, int n_in,
                              void* d_out, int out_size)
{
    const int*   ids  = (const int*)d_in[0];
    const int*   am   = (const int*)d_in[1];
    const int*   tt   = (const int*)d_in[2];
    const int*   yt   = (const int*)d_in[3];
    const float* wemb = (const float*)d_in[4];
    const float* pemb = (const float*)d_in[5];
    const float* temb = (const float*)d_in[6];
    const float* eg   = (const float*)d_in[7];
    const float* eb   = (const float*)d_in[8];
    const float* Wq   = (const float*)d_in[9];
    const float* bq   = (const float*)d_in[10];
    const float* Wk   = (const float*)d_in[11];
    const float* bk   = (const float*)d_in[12];
    const float* Wv   = (const float*)d_in[13];
    const float* bv   = (const float*)d_in[14];
    const float* Wo   = (const float*)d_in[15];
    const float* bo   = (const float*)d_in[16];
    const float* l1g  = (const float*)d_in[17];
    const float* l1b  = (const float*)d_in[18];
    const float* W1   = (const float*)d_in[19];
    const float* b1   = (const float*)d_in[20];
    const float* W2   = (const float*)d_in[21];
    const float* b2   = (const float*)d_in[22];
    const float* l2g  = (const float*)d_in[23];
    const float* l2b  = (const float*)d_in[24];
    const float* hW   = (const float*)d_in[25];
    const float* hb   = (const float*)d_in[26];
    const float* cs   = (const float*)d_in[27];
    const float* ce   = (const float*)d_in[28];
    const float* ctr  = (const float*)d_in[29];

    static float *p_h = nullptr, *p_ctx, *p_tmp, *p_ffn;
    if (!p_h) {
        cudaGetSymbolAddress((void**)&p_h,   g_h);
        cudaGetSymbolAddress((void**)&p_ctx, g_ctx);
        cudaGetSymbolAddress((void**)&p_tmp, g_tmp);
        cudaGetSymbolAddress((void**)&p_ffn, g_ffn);
        cudaFuncSetAttribute(attn_kernel, cudaFuncAttributeMaxDynamicSharedMemorySize,
                             ATTN_SMEM_FLOATS * 4);
        cudaFuncSetAttribute(gemm_mma, cudaFuncAttributeMaxDynamicSharedMemorySize,
                             GT_SMEM);
    }

    embed_ln_kernel<<<NTOK, 192>>>(ids, tt, wemb, pemb, temb, eg, eb);

    dim3 gG_qkv(QKVS / 64, NTOK / 64);     // 36 x 64
    dim3 gG_dm(DM_ / 64, NTOK / 64);       // 12 x 64
    dim3 gG_ff(FF_ / 64, NTOK / 64);       // 48 x 64

    for (int l = 0; l < NL_; l++) {
        size_t wOff = (size_t)l * DM_ * DM_;
        // ---- fused QKV: C = h @ [Wq|Wk|Wv] + [bq|bk|bv] ----
        gemm_mma<<<gG_qkv, 128, GT_SMEM>>>(p_h, Wq + wOff, Wk + wOff, Wv + wOff,
                                           bq + l * DM_, bk + l * DM_, bv + l * DM_,
                                           p_ffn, DM_, QKVS, 768, 0);
        // ---- attention ----
        attn_kernel<<<dim3(NH_, B_), 256, ATTN_SMEM_FLOATS * 4>>>(am);
        // ---- output proj ----
        gemm_mma<<<gG_dm, 128, GT_SMEM>>>(p_ctx, Wo + wOff, Wo + wOff, Wo + wOff,
                                          bo + l * DM_, bo + l * DM_, bo + l * DM_,
                                          p_tmp, DM_, DM_, DM_, 0);
        add_ln_kernel<<<NTOK, 192>>>(l1g + l * DM_, l1b + l * DM_);
        // ---- FFN ----
        gemm_mma<<<gG_ff, 128, GT_SMEM>>>(p_h, W1 + (size_t)l * DM_ * FF_,
                                          W1 + (size_t)l * DM_ * FF_,
                                          W1 + (size_t)l * DM_ * FF_,
                                          b1 + l * FF_, b1 + l * FF_, b1 + l * FF_,
                                          p_ffn, DM_, FF_, FF_, 1);
        gemm_mma<<<gG_dm, 128, GT_SMEM>>>(p_ffn, W2 + (size_t)l * FF_ * DM_,
                                          W2 + (size_t)l * FF_ * DM_,
                                          W2 + (size_t)l * FF_ * DM_,
                                          b2 + l * DM_, b2 + l * DM_, b2 + l * DM_,
                                          p_tmp, FF_, DM_, DM_, 0);
        add_ln_kernel<<<NTOK, 192>>>(l2g + l * DM_, l2b + l * DM_);
    }

    head_kernel<<<dim3(T_, B_), 288>>>(hW, hb);
    crf_kernel<<<B_, 32>>>(am, yt, cs, ce, ctr, (float*)d_out, out_size);
}